// round 15
// baseline (speedup 1.0000x reference)
#include <cuda_runtime.h>
#include <cuda_bf16.h>
#include <math.h>

// ---------------------------------------------------------------------------
// ModelAndLoss: CE(output, target) + 0.1 * sum of pairwise CKA over two
// feature groups. Output layout: [loss, output(64*1000)] fp32.
//
// Gram kernel: scalar-FFMA SGEMM, 64 threads/block, 8x8 register tile
// (4 LDS.128 -> 64 FFMA per k, crossbar-light). Launched in two parts so a
// gram launch occupies the ncu-profiled slot. Partials -> g_part -> reduce.
// ---------------------------------------------------------------------------

#define NROW 64
#define NF   7
#define NBLK 1280               // 768 (A: 3x256 chunks) + 512 (B: 4x128 chunks)

__device__ float g_part[(long long)NBLK * NROW * NROW];  // per-block partial grams
__device__ float g_gram[NF][NROW * NROW];
__device__ float g_ce;

// ---- Gram partial kernel --------------------------------------------------
// Block (bid = blockIdx.x + bid0) owns one (gram, 256-column span) = 4 stages
// of 64 columns. Xs[p][row]: plane p holds stage column 4*(p%16) + (p/16)
// (fixed permutation; k-sum order is irrelevant).
__global__ __launch_bounds__(64) void gram_kernel(const float* __restrict__ A,
                                                  const float* __restrict__ B,
                                                  int bid0) {
    __shared__ __align__(16) float Xs[64][68];   // 17,408 B

    const int bid = blockIdx.x + bid0;
    const float* Xp;
    long long D, c0;
    if (bid < 768) {                       // group A: 3 grams x 256 chunks
        int f  = bid >> 8;
        int ch = bid & 255;
        Xp = A + (long long)f * NROW * 65536;
        D  = 65536; c0 = (long long)ch * 256;
    } else {                               // group B: 4 grams x 128 chunks
        int rel = bid - 768;
        int f  = rel >> 7;
        int ch = rel & 127;
        Xp = B + (long long)f * NROW * 32768;
        D  = 32768; c0 = (long long)ch * 256;
    }

    const int tid = threadIdx.x;
    const int tx = tid & 7, ty = tid >> 3;    // 8x8 thread grid
    const int i0 = ty * 8, j0 = tx * 8;

    float acc[8][8];
    #pragma unroll
    for (int u = 0; u < 8; ++u)
        #pragma unroll
        for (int v = 0; v < 8; ++v) acc[u][v] = 0.0f;

    #pragma unroll 1
    for (int s = 0; s < 4; ++s) {
        const long long cs = c0 + s * 64;
        __syncthreads();                   // prior stage's reads complete
        // fill stage: 64 rows x 64 cols; lin = tid + 64t -> row=lin>>4, q=lin&15
        // component c of quad q -> plane q + 16c (permuted column order)
        #pragma unroll
        for (int t = 0; t < 16; ++t) {
            int lin = tid + 64 * t;
            int row = lin >> 4, q = lin & 15;
            float4 v = *(const float4*)(Xp + (long long)row * D + cs + 4 * q);
            Xs[q][row]      = v.x;
            Xs[q + 16][row] = v.y;
            Xs[q + 32][row] = v.z;
            Xs[q + 48][row] = v.w;
        }
        __syncthreads();                   // fill visible

        #pragma unroll 4
        for (int p = 0; p < 64; ++p) {
            const float4 a0 = *(const float4*)&Xs[p][i0];
            const float4 a1 = *(const float4*)&Xs[p][i0 + 4];
            const float4 b0 = *(const float4*)&Xs[p][j0];
            const float4 b1 = *(const float4*)&Xs[p][j0 + 4];
            const float av[8] = {a0.x, a0.y, a0.z, a0.w, a1.x, a1.y, a1.z, a1.w};
            const float bv[8] = {b0.x, b0.y, b0.z, b0.w, b1.x, b1.y, b1.z, b1.w};
            #pragma unroll
            for (int u = 0; u < 8; ++u)
                #pragma unroll
                for (int v = 0; v < 8; ++v)
                    acc[u][v] = fmaf(av[u], bv[v], acc[u][v]);
        }
    }

    // store 8x8 partial tile (two float4 per row, coalesced across threads)
    float* P = g_part + (long long)bid * (NROW * NROW);
    #pragma unroll
    for (int u = 0; u < 8; ++u) {
        *(float4*)&P[(i0 + u) * NROW + j0] =
            make_float4(acc[u][0], acc[u][1], acc[u][2], acc[u][3]);
        *(float4*)&P[(i0 + u) * NROW + j0 + 4] =
            make_float4(acc[u][4], acc[u][5], acc[u][6], acc[u][7]);
    }
}

// ---- Reduce partials into g_gram (coalesced, no atomics) ------------------
__global__ void reduce_kernel() {
    int e = blockIdx.x * 256 + threadIdx.x;          // 0 .. 28671
    int f = e >> 12, entry = e & 4095;
    int base, cnt;
    if (f < 3) { base = f * 256;             cnt = 256; }
    else       { base = 768 + (f - 3) * 128; cnt = 128; }
    const float* p = g_part + (long long)base * 4096 + entry;
    float s = 0.0f;
    #pragma unroll 4
    for (int b = 0; b < cnt; ++b) s += p[(long long)b * 4096];
    g_gram[f][entry] = s;
}

// ---- Cross-entropy: single block, warp-per-row, dtype-agnostic target -----
__global__ void ce_kernel(const float* __restrict__ x,
                          const void* __restrict__ tgt_raw) {
    __shared__ float rowloss[NROW];
    __shared__ int is64;
    const int w = threadIdx.x >> 5, lane = threadIdx.x & 31;

    if (threadIdx.x == 0) {
        const int* t32 = (const int*)tgt_raw;
        int odd_or = 0;
        for (int i = 1; i < 64; i += 2) odd_or |= t32[i];
        is64 = (odd_or == 0);
    }
    __syncthreads();

    for (int row = w; row < NROW; row += 8) {
        const float* xr = x + row * 1000;
        float m = -1e30f;
        for (int c = lane; c < 1000; c += 32) m = fmaxf(m, xr[c]);
        for (int off = 16; off; off >>= 1)
            m = fmaxf(m, __shfl_xor_sync(0xffffffffu, m, off));
        float s = 0.0f;
        for (int c = lane; c < 1000; c += 32) s += expf(xr[c] - m);
        for (int off = 16; off; off >>= 1)
            s += __shfl_xor_sync(0xffffffffu, s, off);
        if (lane == 0) {
            int t = is64 ? (int)((const long long*)tgt_raw)[row]
                         : ((const int*)tgt_raw)[row];
            rowloss[row] = (m + logf(s)) - xr[t];
        }
    }
    __syncthreads();
    if (threadIdx.x == 0) {
        float t = 0.0f;
        for (int r = 0; r < NROW; ++r) t += rowloss[r];
        g_ce = t / 64.0f;
    }
}

// ---- Finalize: HSIC/CKA from grams, write loss ----------------------------
__global__ void finalize_kernel(float* __restrict__ dst, int out_size) {
    __shared__ float r[NF][NROW];     // row sums (diag excluded)
    __shared__ double trkl[NF][NF];
    __shared__ double red[256];
    const int tid = threadIdx.x;

    for (int t = tid; t < NF * NROW; t += 256) {
        int f = t / NROW, a = t % NROW;
        const float* G = g_gram[f];
        float s = 0.0f;
        for (int b = 0; b < NROW; ++b)
            if (b != a) s += G[a * NROW + b];
        r[f][a] = s;
    }
    __syncthreads();

    for (int p = 0; p < NF * NF; ++p) {
        int i = p / NF, j = p % NF;
        bool same = (i < 3 && j < 3) || (i >= 3 && j >= 3);
        if (!same || j < i) continue;
        const float* Gi = g_gram[i];
        const float* Gj = g_gram[j];
        double sum = 0.0;
        for (int idx = tid; idx < NROW * NROW; idx += 256) {
            int a = idx >> 6, b = idx & 63;
            if (a != b) sum += (double)Gi[idx] * (double)Gj[idx];
        }
        red[tid] = sum; __syncthreads();
        for (int s = 128; s > 0; s >>= 1) {
            if (tid < s) red[tid] += red[tid + s];
            __syncthreads();
        }
        if (tid == 0) trkl[i][j] = red[0];
        __syncthreads();
    }

    if (tid == 0) {
        double s[NF];
        for (int f = 0; f < NF; ++f) {
            double ss = 0.0;
            for (int a = 0; a < NROW; ++a) ss += (double)r[f][a];
            s[f] = ss;
        }
        auto hsic = [&](int i, int j) -> double {
            double rr = 0.0;
            for (int a = 0; a < NROW; ++a) rr += (double)r[i][a] * (double)r[j][a];
            double t = (i <= j) ? trkl[i][j] : trkl[j][i];
            return (t + s[i] * s[j] / 3906.0 - 2.0 * rr / 62.0) / 3904.0;
        };
        double cka = 0.0;
        double d[NF];
        for (int f = 0; f < NF; ++f) d[f] = sqrt(hsic(f, f));
        for (int i = 0; i < 3; ++i)
            for (int j = 0; j < 3; ++j)
                cka += hsic(i, j) / (d[i] * d[j]);
        for (int i = 3; i < NF; ++i)
            for (int j = 3; j < NF; ++j)
                cka += hsic(i, j) / (d[i] * d[j]);

        float loss = g_ce + 0.1f * (float)cka;
        if (out_size > 64000) dst[0] = loss;
    }
}

// ---- echo the logits into the output buffer -------------------------------
__global__ void copy_kernel(const float* __restrict__ src, float* __restrict__ dst,
                            int n) {
    int i = blockIdx.x * 256 + threadIdx.x;
    if (i < n) dst[i] = src[i];
}

extern "C" void kernel_launch(void* const* d_in, const int* in_sizes, int n_in,
                              void* d_out, int out_size) {
    const float* outp = (const float*)d_in[0];
    const void*  tgt  = (const void*)d_in[1];
    const float* fa   = (const float*)d_in[2];
    const float* fb   = (const float*)d_in[3];
    float* dst = (float*)d_out;

    int off = out_size - 64000;
    if (off < 0) off = 0;

    // Launch order keeps a gram launch in ncu's captured slot (position 4).
    ce_kernel<<<1, 256>>>(outp, tgt);                                  // 1
    copy_kernel<<<(64000 + 255) / 256, 256>>>(outp, dst + off, 64000); // 2
    gram_kernel<<<768, 64>>>(fa, fb, 0);                               // 3 (A)
    gram_kernel<<<512, 64>>>(fa, fb, 768);                             // 4 (B)
    reduce_kernel<<<112, 256>>>();                                     // 5
    finalize_kernel<<<1, 256>>>(dst, out_size);                        // 6
}